// round 15
// baseline (speedup 1.0000x reference)
#include <cuda_runtime.h>
#include <cuda_fp16.h>
#include <cstdint>
#include <math.h>

#define FD 512
#define RD 196
#define RP 224
#define VDIM 300
#define NI 1000
#define NIPAD 1024
#define NB 256

// ---- gemm1sel smem map ----
#define G1_STAGE 28160          // per-stage: QH 128x80B @0, BH 224x80B @10240
#define G1_BH    10240
#define REDM_OFF 56320          // 128 rows x 4 floats
#define SMEM_REQ1 58368

#define NHB 28672               // hsplit blocks (7*16*256)

__device__ __align__(16) __half g_qh[NIPAD * FD];                 // q hi (GEMM1 A)
__device__ __align__(16) float  g_q32[NIPAD * FD];                // q fp32 (exact dot)
__device__ __align__(16) __half g_th[(size_t)NB * RP * FD];       // Ht hi [b][r][f] (GEMM1 B)
__device__ __align__(16) float  g_tf[(size_t)NB * RP * FD];       // Ht fp32 [b][r][f] (gather)
__device__ __align__(16) unsigned long long g_mask[(size_t)NB * NIPAD * 4];  // 56-bit chunks
__device__ __align__(16) float  g_rowmax[(size_t)NB * NIPAD];     // approx row max

// ---------------- PTX helpers ----------------
__device__ __forceinline__ uint32_t smem_u32(const void* p) {
    uint32_t a;
    asm("{ .reg .u64 t; cvta.to.shared.u64 t, %1; cvt.u32.u64 %0, t; }" : "=r"(a) : "l"(p));
    return a;
}
__device__ __forceinline__ void cpa16(uint32_t d, const void* s) {
    asm volatile("cp.async.cg.shared.global [%0], [%1], 16;" :: "r"(d), "l"(s));
}
#define CP_COMMIT() asm volatile("cp.async.commit_group;")
__device__ __forceinline__ void ldsm4(uint32_t* r, uint32_t a) {
    asm volatile("ldmatrix.sync.aligned.m8n8.x4.shared.b16 {%0,%1,%2,%3},[%4];"
        : "=r"(r[0]), "=r"(r[1]), "=r"(r[2]), "=r"(r[3]) : "r"(a));
}
__device__ __forceinline__ void ldsm2(uint32_t* r, uint32_t a) {
    asm volatile("ldmatrix.sync.aligned.m8n8.x2.shared.b16 {%0,%1},[%2];"
        : "=r"(r[0]), "=r"(r[1]) : "r"(a));
}
__device__ __forceinline__ void mma_f16(uint32_t* d, const uint32_t* a, uint32_t b0, uint32_t b1) {
    asm volatile("mma.sync.aligned.m16n8k16.row.col.f16.f16.f16.f16 "
        "{%0,%1},{%2,%3,%4,%5},{%6,%7},{%0,%1};"
        : "+r"(d[0]), "+r"(d[1])
        : "r"(a[0]), "r"(a[1]), "r"(a[2]), "r"(a[3]), "r"(b0), "r"(b1));
}
__device__ __forceinline__ void addcorr(float* a4, uint32_t* c2) {
    float2 f0 = __half22float2(*reinterpret_cast<const __half2*>(&c2[0]));
    float2 f1 = __half22float2(*reinterpret_cast<const __half2*>(&c2[1]));
    a4[0] += f0.x; a4[1] += f0.y; a4[2] += f1.x; a4[3] += f1.y;
    c2[0] = 0u; c2[1] = 0u;
}

// ---------------- merged prep: hsplit blocks [0,NHB) + qgemm blocks [NHB,NHB+512) ----------------
__global__ __launch_bounds__(256) void prep(
    const float* __restrict__ h, const float* __restrict__ vecs,
    const float* __restrict__ w_g)
{
    __shared__ float sbuf[8 * VDIM];   // max(32*33=1056, 8*300=2400) floats
    const int tid = threadIdx.x;
    if (blockIdx.x < NHB) {
        // ---- hsplit role ----
        const int idx = blockIdx.x;
        const int r0 = (idx % 7) * 32;
        const int f0 = ((idx / 7) & 15) * 32;
        const int b  = idx / 112;
        const int tx = tid & 31, ty = tid >> 5;
        float* t = sbuf;
#pragma unroll
        for (int s = 0; s < 4; s++) {
            int fl = ty + 8 * s, r = r0 + tx;
            t[fl * 33 + tx] = (r < RD) ? h[((size_t)b * FD + f0 + fl) * RD + r] : 0.0f;
        }
        __syncthreads();
#pragma unroll
        for (int s = 0; s < 4; s++) {
            int rl = ty + 8 * s;
            float v = t[tx * 33 + rl];
            size_t o = ((size_t)b * RP + r0 + rl) * FD + f0 + tx;
            g_th[o] = __float2half_rn(v);
            g_tf[o] = v;
        }
    } else {
        // ---- qgemm role: 8 i-rows x 128 f-cols, first 128 threads active ----
        const int idx2 = blockIdx.x - NHB;
        const int f = (idx2 & 3) * 128 + (tid & 127);
        const int i0 = (idx2 >> 2) * 8;
        float* vs = sbuf;   // [8][300]
        for (int e = tid; e < 8 * VDIM; e += 256) {
            int ii = e / VDIM, v = e % VDIM, i = i0 + ii;
            vs[ii * VDIM + v] = (i < NI) ? vecs[i * VDIM + v] : 0.0f;
        }
        __syncthreads();
        if (tid < 128) {
            float acc[8];
#pragma unroll
            for (int ii = 0; ii < 8; ii++) acc[ii] = 0.0f;
#pragma unroll 4
            for (int v = 0; v < VDIM; v++) {
                float w = w_g[v * FD + f];
#pragma unroll
                for (int ii = 0; ii < 8; ii++) acc[ii] += vs[ii * VDIM + v] * w;
            }
#pragma unroll
            for (int ii = 0; ii < 8; ii++) {
                size_t o = (size_t)(i0 + ii) * FD + f;
                g_qh[o] = __float2half_rn(acc[ii]);
                g_q32[o] = acc[ii];
            }
        }
    }
}

// ---------------- GEMM1 stage loader (hi only) ----------------
__device__ __forceinline__ void issue_g1(uint32_t sb,
    const __half* qh, const __half* th, int c, int tid)
{
    const int ko = c * 32;
    for (int t = tid; t < 512; t += 256) {
        int row = t >> 2, cc = t & 3;
        cpa16(sb + row * 80 + cc * 16, qh + row * FD + ko + cc * 8);
    }
    for (int t = tid; t < 896; t += 256) {
        int row = t >> 2, cc = t & 3;
        cpa16(sb + G1_BH + row * 80 + cc * 16, th + row * FD + ko + cc * 8);
    }
}

// ---------------- kernel 2: GEMM1 (f16-acc, chunk-folded) + mask/rowmax epilogue ----------------
__global__ __launch_bounds__(256) void gemm1sel()
{
    extern __shared__ char sm[];
    const uint32_t sbase = smem_u32(sm);
    float* redm = reinterpret_cast<float*>(sm + REDM_OFF);

    const int tid = threadIdx.x, lane = tid & 31, wid = tid >> 5;
    const int mw = wid >> 2, nw = wid & 3;
    const int b = blockIdx.y, i0 = blockIdx.x * 128;

    const __half* qh = g_qh + (size_t)i0 * FD;
    const __half* th = g_th + (size_t)b * RP * FD;

    const int arow = (lane & 7) + ((lane >> 3) & 1) * 8;
    const int acg  = (lane >> 4) * 16;

    float acc[4][7][4];
    uint32_t cor[4][7][2];
#pragma unroll
    for (int mf = 0; mf < 4; mf++)
#pragma unroll
        for (int nf = 0; nf < 7; nf++) {
#pragma unroll
            for (int e = 0; e < 4; e++) acc[mf][nf][e] = 0.0f;
            cor[mf][nf][0] = 0u; cor[mf][nf][1] = 0u;
        }

    issue_g1(sbase, qh, th, 0, tid);
    CP_COMMIT();
    for (int c = 0; c < 16; c++) {
        const uint32_t st = sbase + (uint32_t)(c & 1) * G1_STAGE;
        if (c < 15) {
            issue_g1(sbase + (uint32_t)((c + 1) & 1) * G1_STAGE, qh, th, c + 1, tid);
            CP_COMMIT();
            asm volatile("cp.async.wait_group 1;");
        } else {
            asm volatile("cp.async.wait_group 0;");
        }
        __syncthreads();
#pragma unroll
        for (int kk = 0; kk < 2; kk++) {
            uint32_t ah[4][4];
#pragma unroll
            for (int mf = 0; mf < 4; mf++) {
                uint32_t ad = st + (uint32_t)(mw * 64 + mf * 16 + arow) * 80 + kk * 32 + acg;
                ldsm4(ah[mf], ad);
            }
#pragma unroll
            for (int p = 0; p < 3; p++) {
                uint32_t bd = st + G1_BH + (uint32_t)(nw * 56 + p * 16 + arow) * 80 + kk * 32 + acg;
                uint32_t bh[4];
                ldsm4(bh, bd);
#pragma unroll
                for (int mf = 0; mf < 4; mf++) {
                    mma_f16(cor[mf][2 * p],     ah[mf], bh[0], bh[2]);
                    mma_f16(cor[mf][2 * p + 1], ah[mf], bh[1], bh[3]);
                }
            }
            {
                uint32_t bd = st + G1_BH + (uint32_t)(nw * 56 + 48 + (lane & 7)) * 80
                              + kk * 32 + ((lane >> 3) & 1) * 16;
                uint32_t bh[2];
                ldsm2(bh, bd);
#pragma unroll
                for (int mf = 0; mf < 4; mf++)
                    mma_f16(cor[mf][6], ah[mf], bh[0], bh[1]);
            }
        }
        if ((c & 3) == 3) {
#pragma unroll
            for (int mf = 0; mf < 4; mf++)
#pragma unroll
                for (int nf = 0; nf < 7; nf++) addcorr(acc[mf][nf], cor[mf][nf]);
        }
        __syncthreads();
    }

    // ---- epilogue: per-row max (cross-warp), rowmax store, 56-bit candidate mask ----
    const int qlane = lane >> 2, plane = 2 * (lane & 3);
#pragma unroll
    for (int mf = 0; mf < 4; mf++)
#pragma unroll
        for (int hh = 0; hh < 2; hh++) {
            float mx = -INFINITY;
#pragma unroll
            for (int nf = 0; nf < 7; nf++)
#pragma unroll
                for (int e = 0; e < 2; e++) {
                    int col = nw * 56 + nf * 8 + plane + e;
                    if (col < RD) mx = fmaxf(mx, acc[mf][nf][2 * hh + e]);
                }
            mx = fmaxf(mx, __shfl_xor_sync(0xffffffffu, mx, 1));
            mx = fmaxf(mx, __shfl_xor_sync(0xffffffffu, mx, 2));
            if ((lane & 3) == 0) {
                int row = mw * 64 + mf * 16 + qlane + hh * 8;
                redm[row * 4 + nw] = mx;
            }
        }
    __syncthreads();
#pragma unroll
    for (int mf = 0; mf < 4; mf++)
#pragma unroll
        for (int hh = 0; hh < 2; hh++) {
            int row = mw * 64 + mf * 16 + qlane + hh * 8;
            float M = fmaxf(fmaxf(redm[row * 4], redm[row * 4 + 1]),
                            fmaxf(redm[row * 4 + 2], redm[row * 4 + 3]));
            float thr = M - 24.0f;
            unsigned long long mb = 0ull;
#pragma unroll
            for (int nf = 0; nf < 7; nf++)
#pragma unroll
                for (int e = 0; e < 2; e++) {
                    int col = nw * 56 + nf * 8 + plane + e;
                    if (col < RD && acc[mf][nf][2 * hh + e] > thr)
                        mb |= 1ull << (nf * 8 + plane + e);
                }
            mb |= __shfl_xor_sync(0xffffffffu, mb, 1);
            mb |= __shfl_xor_sync(0xffffffffu, mb, 2);
            if ((lane & 3) == 0) {
                g_mask[((size_t)b * NIPAD + i0 + row) * 4 + nw] = mb;
                if (nw == 0) g_rowmax[(size_t)b * NIPAD + i0 + row] = M;
            }
        }
}

// ---------------- kernel 3: high-occupancy exact softmax-gather (no rescale) ----------------
// grid (125, 256), 256 threads: one warp per (b, i) row
__global__ __launch_bounds__(256) void gather(float* __restrict__ out)
{
    const int lane = threadIdx.x & 31, wid = threadIdx.x >> 5;
    const int b = blockIdx.y;
    const int i = blockIdx.x * 8 + wid;          // 125*8 = 1000 exactly

    const size_t gr = (size_t)b * NIPAD + i;
    const float M = g_rowmax[gr];                 // fixed softmax reference (+-1 of true max)
    const float* q32 = g_q32 + (size_t)i * FD;
    float qr[16];
#pragma unroll
    for (int k = 0; k < 16; k++) qr[k] = q32[lane + 32 * k];

    float ssum = 0.0f;
    float eg[16];
#pragma unroll
    for (int k = 0; k < 16; k++) eg[k] = 0.0f;

#pragma unroll 1
    for (int j = 0; j < 4; j++) {
        unsigned long long bs = g_mask[gr * 4 + j];
        while (bs) {
            int p = __ffsll(bs) - 1; bs &= bs - 1;
            int c = j * 56 + p;
            const float* hp = g_tf + ((size_t)b * RP + c) * FD;
            float hr[16];
#pragma unroll
            for (int k = 0; k < 16; k++) hr[k] = hp[lane + 32 * k];
            float s = 0.0f;
#pragma unroll
            for (int k = 0; k < 16; k++) s += qr[k] * hr[k];
#pragma unroll
            for (int o = 16; o > 0; o >>= 1) s += __shfl_xor_sync(0xffffffffu, s, o);
            float w = __expf(s - M);              // bounded: s-M in [-25, ~1.5]
            ssum += w;
#pragma unroll
            for (int k = 0; k < 16; k++) eg[k] += w * hr[k];
        }
    }
    const float inv = 1.0f / ssum;
    float* op = out + ((size_t)b * NI + i) * FD;
#pragma unroll
    for (int k = 0; k < 16; k++) __stcs(op + lane + 32 * k, eg[k] * inv);
}

// ---------------------------------------------------------------------------
extern "C" void kernel_launch(void* const* d_in, const int* in_sizes, int n_in,
                              void* d_out, int out_size)
{
    const float* h_r  = (const float*)d_in[0];  // (256, 512, 196)
    const float* vecs = (const float*)d_in[1];  // (1000, 300)
    const float* w_g  = (const float*)d_in[2];  // (300, 512)
    float* out = (float*)d_out;                 // (256, 1000, 512)

    cudaFuncSetAttribute(gemm1sel, cudaFuncAttributeMaxDynamicSharedMemorySize, SMEM_REQ1);

    prep<<<NHB + 512, 256>>>(h_r, vecs, w_g);
    gemm1sel<<<dim3(NIPAD / 128, NB), 256, SMEM_REQ1>>>();
    gather<<<dim3(125, NB), 256>>>(out);
}

// round 16
// speedup vs baseline: 1.0877x; 1.0877x over previous
#include <cuda_runtime.h>
#include <cuda_fp16.h>
#include <cstdint>
#include <math.h>

#define FD 512
#define RD 196
#define RP 224
#define VDIM 300
#define NI 1000
#define NIPAD 1024
#define NB 256

// ---- gemm1sel smem map ----
#define G1_STAGE 28160          // per-stage: QH 128x80B @0, BH 224x80B @10240
#define G1_BH    10240
#define REDM_OFF 56320          // 128 rows x 4 floats
#define SMEM_REQ1 58368

#define NHB 28672               // hsplit blocks (7*16*256)

__device__ __align__(16) __half g_qh[NIPAD * FD];                 // q hi (GEMM1 A)
__device__ __align__(16) float  g_q32[NIPAD * FD];                // q fp32 (exact dot)
__device__ __align__(16) __half g_th[(size_t)NB * RP * FD];       // Ht hi [b][r][f] (GEMM1 B)
__device__ __align__(16) float  g_tf[(size_t)NB * RP * FD];       // Ht fp32 [b][r][f] (gather)
__device__ __align__(16) unsigned long long g_mask[(size_t)NB * NIPAD * 4];  // 56-bit chunks
__device__ __align__(16) float  g_rowmax[(size_t)NB * NIPAD];     // approx row max

// ---------------- PTX helpers ----------------
__device__ __forceinline__ uint32_t smem_u32(const void* p) {
    uint32_t a;
    asm("{ .reg .u64 t; cvta.to.shared.u64 t, %1; cvt.u32.u64 %0, t; }" : "=r"(a) : "l"(p));
    return a;
}
__device__ __forceinline__ void cpa16(uint32_t d, const void* s) {
    asm volatile("cp.async.cg.shared.global [%0], [%1], 16;" :: "r"(d), "l"(s));
}
#define CP_COMMIT() asm volatile("cp.async.commit_group;")
__device__ __forceinline__ void ldsm4(uint32_t* r, uint32_t a) {
    asm volatile("ldmatrix.sync.aligned.m8n8.x4.shared.b16 {%0,%1,%2,%3},[%4];"
        : "=r"(r[0]), "=r"(r[1]), "=r"(r[2]), "=r"(r[3]) : "r"(a));
}
__device__ __forceinline__ void ldsm2(uint32_t* r, uint32_t a) {
    asm volatile("ldmatrix.sync.aligned.m8n8.x2.shared.b16 {%0,%1},[%2];"
        : "=r"(r[0]), "=r"(r[1]) : "r"(a));
}
__device__ __forceinline__ void mma_f16(uint32_t* d, const uint32_t* a, uint32_t b0, uint32_t b1) {
    asm volatile("mma.sync.aligned.m16n8k16.row.col.f16.f16.f16.f16 "
        "{%0,%1},{%2,%3,%4,%5},{%6,%7},{%0,%1};"
        : "+r"(d[0]), "+r"(d[1])
        : "r"(a[0]), "r"(a[1]), "r"(a[2]), "r"(a[3]), "r"(b0), "r"(b1));
}
// unpack element idx (0..3) of an f16 accumulator pair
__device__ __forceinline__ float corval(const uint32_t* c2, int idx) {
    float2 f = __half22float2(*reinterpret_cast<const __half2*>(&c2[idx >> 1]));
    return (idx & 1) ? f.y : f.x;
}

// ---------------- merged prep: hsplit blocks [0,NHB) + qgemm blocks [NHB,NHB+512) ----------------
__global__ __launch_bounds__(256) void prep(
    const float* __restrict__ h, const float* __restrict__ vecs,
    const float* __restrict__ w_g)
{
    __shared__ float sbuf[8 * VDIM];   // max(32*33, 8*300) floats
    const int tid = threadIdx.x;
    if (blockIdx.x < NHB) {
        const int idx = blockIdx.x;
        const int r0 = (idx % 7) * 32;
        const int f0 = ((idx / 7) & 15) * 32;
        const int b  = idx / 112;
        const int tx = tid & 31, ty = tid >> 5;
        float* t = sbuf;
#pragma unroll
        for (int s = 0; s < 4; s++) {
            int fl = ty + 8 * s, r = r0 + tx;
            t[fl * 33 + tx] = (r < RD) ? h[((size_t)b * FD + f0 + fl) * RD + r] : 0.0f;
        }
        __syncthreads();
#pragma unroll
        for (int s = 0; s < 4; s++) {
            int rl = ty + 8 * s;
            float v = t[tx * 33 + rl];
            size_t o = ((size_t)b * RP + r0 + rl) * FD + f0 + tx;
            g_th[o] = __float2half_rn(v);
            g_tf[o] = v;
        }
    } else {
        const int idx2 = blockIdx.x - NHB;
        const int f = (idx2 & 3) * 128 + (tid & 127);
        const int i0 = (idx2 >> 2) * 8;
        float* vs = sbuf;
        for (int e = tid; e < 8 * VDIM; e += 256) {
            int ii = e / VDIM, v = e % VDIM, i = i0 + ii;
            vs[ii * VDIM + v] = (i < NI) ? vecs[i * VDIM + v] : 0.0f;
        }
        __syncthreads();
        if (tid < 128) {
            float acc[8];
#pragma unroll
            for (int ii = 0; ii < 8; ii++) acc[ii] = 0.0f;
#pragma unroll 4
            for (int v = 0; v < VDIM; v++) {
                float w = w_g[v * FD + f];
#pragma unroll
                for (int ii = 0; ii < 8; ii++) acc[ii] += vs[ii * VDIM + v] * w;
            }
#pragma unroll
            for (int ii = 0; ii < 8; ii++) {
                size_t o = (size_t)(i0 + ii) * FD + f;
                g_qh[o] = __float2half_rn(acc[ii]);
                g_q32[o] = acc[ii];
            }
        }
    }
}

// ---------------- GEMM1 stage loader (hi only) ----------------
__device__ __forceinline__ void issue_g1(uint32_t sb,
    const __half* qh, const __half* th, int c, int tid)
{
    const int ko = c * 32;
    for (int t = tid; t < 512; t += 256) {
        int row = t >> 2, cc = t & 3;
        cpa16(sb + row * 80 + cc * 16, qh + row * FD + ko + cc * 8);
    }
    for (int t = tid; t < 896; t += 256) {
        int row = t >> 2, cc = t & 3;
        cpa16(sb + G1_BH + row * 80 + cc * 16, th + row * FD + ko + cc * 8);
    }
}

// ---------------- kernel 2: GEMM1 pure-f16 acc + mask/rowmax epilogue; 2 CTA/SM ----------------
__global__ __launch_bounds__(256, 2) void gemm1sel()
{
    extern __shared__ char sm[];
    const uint32_t sbase = smem_u32(sm);
    float* redm = reinterpret_cast<float*>(sm + REDM_OFF);

    const int tid = threadIdx.x, lane = tid & 31, wid = tid >> 5;
    const int mw = wid >> 2, nw = wid & 3;
    const int b = blockIdx.y, i0 = blockIdx.x * 128;

    const __half* qh = g_qh + (size_t)i0 * FD;
    const __half* th = g_th + (size_t)b * RP * FD;

    const int arow = (lane & 7) + ((lane >> 3) & 1) * 8;
    const int acg  = (lane >> 4) * 16;

    uint32_t cor[4][7][2];
#pragma unroll
    for (int mf = 0; mf < 4; mf++)
#pragma unroll
        for (int nf = 0; nf < 7; nf++) { cor[mf][nf][0] = 0u; cor[mf][nf][1] = 0u; }

    issue_g1(sbase, qh, th, 0, tid);
    CP_COMMIT();
    for (int c = 0; c < 16; c++) {
        const uint32_t st = sbase + (uint32_t)(c & 1) * G1_STAGE;
        if (c < 15) {
            issue_g1(sbase + (uint32_t)((c + 1) & 1) * G1_STAGE, qh, th, c + 1, tid);
            CP_COMMIT();
            asm volatile("cp.async.wait_group 1;");
        } else {
            asm volatile("cp.async.wait_group 0;");
        }
        __syncthreads();
#pragma unroll
        for (int kk = 0; kk < 2; kk++) {
            uint32_t ah[4][4];
#pragma unroll
            for (int mf = 0; mf < 4; mf++) {
                uint32_t ad = st + (uint32_t)(mw * 64 + mf * 16 + arow) * 80 + kk * 32 + acg;
                ldsm4(ah[mf], ad);
            }
#pragma unroll
            for (int p = 0; p < 3; p++) {
                uint32_t bd = st + G1_BH + (uint32_t)(nw * 56 + p * 16 + arow) * 80 + kk * 32 + acg;
                uint32_t bh[4];
                ldsm4(bh, bd);
#pragma unroll
                for (int mf = 0; mf < 4; mf++) {
                    mma_f16(cor[mf][2 * p],     ah[mf], bh[0], bh[2]);
                    mma_f16(cor[mf][2 * p + 1], ah[mf], bh[1], bh[3]);
                }
            }
            {
                uint32_t bd = st + G1_BH + (uint32_t)(nw * 56 + 48 + (lane & 7)) * 80
                              + kk * 32 + ((lane >> 3) & 1) * 16;
                uint32_t bh[2];
                ldsm2(bh, bd);
#pragma unroll
                for (int mf = 0; mf < 4; mf++)
                    mma_f16(cor[mf][6], ah[mf], bh[0], bh[1]);
            }
        }
        __syncthreads();
    }

    // ---- epilogue sweep 1: per-row max (unpack f16 on the fly) ----
    const int qlane = lane >> 2, plane = 2 * (lane & 3);
#pragma unroll
    for (int mf = 0; mf < 4; mf++)
#pragma unroll
        for (int hh = 0; hh < 2; hh++) {
            float mx = -INFINITY;
#pragma unroll
            for (int nf = 0; nf < 7; nf++)
#pragma unroll
                for (int e = 0; e < 2; e++) {
                    int col = nw * 56 + nf * 8 + plane + e;
                    if (col < RD) mx = fmaxf(mx, corval(cor[mf][nf], 2 * hh + e));
                }
            mx = fmaxf(mx, __shfl_xor_sync(0xffffffffu, mx, 1));
            mx = fmaxf(mx, __shfl_xor_sync(0xffffffffu, mx, 2));
            if ((lane & 3) == 0) {
                int row = mw * 64 + mf * 16 + qlane + hh * 8;
                redm[row * 4 + nw] = mx;
            }
        }
    __syncthreads();
    // ---- epilogue sweep 2: candidate mask + rowmax ----
#pragma unroll
    for (int mf = 0; mf < 4; mf++)
#pragma unroll
        for (int hh = 0; hh < 2; hh++) {
            int row = mw * 64 + mf * 16 + qlane + hh * 8;
            float M = fmaxf(fmaxf(redm[row * 4], redm[row * 4 + 1]),
                            fmaxf(redm[row * 4 + 2], redm[row * 4 + 3]));
            float thr = M - 26.0f;
            unsigned long long mb = 0ull;
#pragma unroll
            for (int nf = 0; nf < 7; nf++)
#pragma unroll
                for (int e = 0; e < 2; e++) {
                    int col = nw * 56 + nf * 8 + plane + e;
                    if (col < RD && corval(cor[mf][nf], 2 * hh + e) > thr)
                        mb |= 1ull << (nf * 8 + plane + e);
                }
            mb |= __shfl_xor_sync(0xffffffffu, mb, 1);
            mb |= __shfl_xor_sync(0xffffffffu, mb, 2);
            if ((lane & 3) == 0) {
                g_mask[((size_t)b * NIPAD + i0 + row) * 4 + nw] = mb;
                if (nw == 0) g_rowmax[(size_t)b * NIPAD + i0 + row] = M;
            }
        }
}

// ---------------- kernel 3: softmax-gather, low-reg, fixed reference ----------------
// grid (125, 256), 256 threads: one warp per (b, i) row
__global__ __launch_bounds__(256, 5) void gather(float* __restrict__ out)
{
    const int lane = threadIdx.x & 31, wid = threadIdx.x >> 5;
    const int b = blockIdx.y;
    const int i = blockIdx.x * 8 + wid;          // 125*8 = 1000 exactly

    const size_t gr = (size_t)b * NIPAD + i;
    const float M = g_rowmax[gr];                 // approx row max (+-~1.5)
    const float* q32 = g_q32 + (size_t)i * FD;    // L2-resident, read per candidate

    float ssum = 0.0f;
    float eg[16];
#pragma unroll
    for (int k = 0; k < 16; k++) eg[k] = 0.0f;

#pragma unroll 1
    for (int j = 0; j < 4; j++) {
        unsigned long long bs = g_mask[gr * 4 + j];
        while (bs) {
            int p = __ffsll(bs) - 1; bs &= bs - 1;
            int c = j * 56 + p;
            const float* hp = g_tf + ((size_t)b * RP + c) * FD;
            float hr[16];
#pragma unroll
            for (int k = 0; k < 16; k++) hr[k] = hp[lane + 32 * k];
            float s = 0.0f;
#pragma unroll
            for (int k = 0; k < 16; k++) s += __ldg(q32 + lane + 32 * k) * hr[k];
#pragma unroll
            for (int o = 16; o > 0; o >>= 1) s += __shfl_xor_sync(0xffffffffu, s, o);
            float w = __expf(s - M);              // bounded
            ssum += w;
#pragma unroll
            for (int k = 0; k < 16; k++) eg[k] += w * hr[k];
        }
    }
    const float inv = 1.0f / ssum;
    float* op = out + ((size_t)b * NI + i) * FD;
#pragma unroll
    for (int k = 0; k < 16; k++) __stcs(op + lane + 32 * k, eg[k] * inv);
}

// ---------------------------------------------------------------------------
extern "C" void kernel_launch(void* const* d_in, const int* in_sizes, int n_in,
                              void* d_out, int out_size)
{
    const float* h_r  = (const float*)d_in[0];  // (256, 512, 196)
    const float* vecs = (const float*)d_in[1];  // (1000, 300)
    const float* w_g  = (const float*)d_in[2];  // (300, 512)
    float* out = (float*)d_out;                 // (256, 1000, 512)

    cudaFuncSetAttribute(gemm1sel, cudaFuncAttributeMaxDynamicSharedMemorySize, SMEM_REQ1);

    prep<<<NHB + 512, 256>>>(h_r, vecs, w_g);
    gemm1sel<<<dim3(NIPAD / 128, NB), 256, SMEM_REQ1>>>();
    gather<<<dim3(125, NB), 256>>>(out);
}